// round 15
// baseline (speedup 1.0000x reference)
#include <cuda_runtime.h>

// PotEnergy1P: out[b] = sum_{i<12,k} exp(-r)/(r+0.01), r = |x[b,i]-nbr[i,k]|
// LUT kernel: v(d2) evaluated by piecewise-linear table in shared memory
// (indexed by exponent + 6 mantissa bits of float(d2), 64 samples/octave,
// range 2^-28..2^13). Inner loop has ZERO MUFU ops: packed-f32x2 d2, then
// per-lane clamp+shift+LDS.64+fma. FAR padding -> sentinel (41,0), whose
// bins are hard-zeroed (u >= 512), so it contributes exactly 0.
// Shape: block 384 = 12 warps (one site per warp), 64 elems/block,
// 2 batch elems per thread (independent chains sharing geometry LDS).

#define NSITES 12
#define NMAX   64
#define NGRP   32              // 2-neighbor groups per site

#define LUT_N      2624        // 41 octaves * 64
#define LUT_ZERO   2368        // idx >= this (u >= 512) -> slope=c=0
#define LOB        0x31800000u // bits(2^-28): lowest covered bin
#define HIB        0x45FE0000u // bits of top bin (idx 2623)
#define IDX_BASE   6336        // (99 << 6): exp field 99 = 2^-28

typedef unsigned long long u64;
typedef unsigned int u32;

__device__ __forceinline__ u64 pk2(float lo, float hi) {
    u64 r; asm("mov.b64 %0, {%1,%2};" : "=l"(r) : "f"(lo), "f"(hi)); return r;
}
__device__ __forceinline__ void upk2(float& lo, float& hi, u64 v) {
    asm("mov.b64 {%0,%1}, %2;" : "=f"(lo), "=f"(hi) : "l"(v));
}
__device__ __forceinline__ u64 addx2(u64 a, u64 b) {
    u64 d; asm("add.rn.f32x2 %0,%1,%2;" : "=l"(d) : "l"(a), "l"(b)); return d;
}
__device__ __forceinline__ u64 mulx2(u64 a, u64 b) {
    u64 d; asm("mul.rn.f32x2 %0,%1,%2;" : "=l"(d) : "l"(a), "l"(b)); return d;
}
__device__ __forceinline__ u64 fmx2(u64 a, u64 b, u64 c) {
    u64 d; asm("fma.rn.f32x2 %0,%1,%2,%3;" : "=l"(d) : "l"(a), "l"(b), "l"(c)); return d;
}
__device__ __forceinline__ u64 pkbits(float lo, float hi) {
    return (u64)__float_as_uint(lo) | ((u64)__float_as_uint(hi) << 32);
}

__global__ __launch_bounds__(384, 5)
void pot_energy_kernel(const float* __restrict__ x,
                       const float* __restrict__ nbr,
                       const float* __restrict__ mask,
                       float* __restrict__ out,
                       int batch)
{
    __shared__ ulonglong2 s_geo[NSITES * NGRP];   // 6 KB
    __shared__ float2     s_lut[LUT_N];           // 21 KB
    __shared__ int        s_ng[NSITES];
    __shared__ float      s_part[NSITES - 1][64]; // 2.75 KB

    if (threadIdx.x < NSITES) s_ng[threadIdx.x] = 0;
    __syncthreads();

    // ---- build geometry (pre-negated; FAR -> sentinel (41,0)) ----
    {
        int j = threadIdx.x;                      // 384 threads, 384 groups
        int base = j * 4;
        float nx0 = nbr[base + 0], ny0 = nbr[base + 1];
        float nx1 = nbr[base + 2], ny1 = nbr[base + 3];
        bool far0 = fabsf(nx0) > 1e5f;
        if (far0)              { nx0 = 41.0f; ny0 = 0.0f; }
        if (fabsf(nx1) > 1e5f) { nx1 = 41.0f; ny1 = 0.0f; }
        ulonglong2 v;
        v.x = pkbits(-nx0, -nx1);
        v.y = pkbits(-ny0, -ny1);
        s_geo[j] = v;
        if (!far0) atomicAdd(&s_ng[j >> 5], 1);   // list is front-packed
    }

    // ---- build LUT: v(u) ~ fmaf(u, slope, c) on [bin_lo, bin_hi) ----
    for (int idx = threadIdx.x; idx < LUT_N; idx += blockDim.x) {
        float2 e;
        if (idx >= LUT_ZERO) {
            e.x = 0.0f; e.y = 0.0f;               // u >= 512: exact zero
        } else {
            u32 lob = (u32)(idx + IDX_BASE) << 17;
            u32 hib = lob + (1u << 17);
            float ulo = __uint_as_float(lob);
            float uhi = __uint_as_float(hib);
            float rlo = sqrtf(ulo), rhi = sqrtf(uhi);
            float flo = expf(-rlo) / (rlo + 0.01f);
            float fhi = expf(-rhi) / (rhi + 0.01f);
            float slope = (fhi - flo) / (uhi - ulo);
            e.x = slope;
            e.y = fmaf(-ulo, slope, flo);         // c = f(lo) - lo*slope
        }
        s_lut[idx] = e;
    }
    __syncthreads();

    const int w    = threadIdx.x >> 5;            // warp = site 0..11
    const int lane = threadIdx.x & 31;
    const int b0   = blockIdx.x * 64 + lane;      // elem A
    const int b1   = b0 + 32;                     // elem B

    float2 v0 = *reinterpret_cast<const float2*>(x + (size_t)b0 * 24 + w * 2);
    float2 v1 = *reinterpret_cast<const float2*>(x + (size_t)b1 * 24 + w * 2);
    u64 xip0 = pk2(v0.x, v0.x);
    u64 yip0 = pk2(v0.y, v0.y);
    u64 xip1 = pk2(v1.x, v1.x);
    u64 yip1 = pk2(v1.y, v1.y);

    // 4 scalar accumulators (one per lane-slot) to decouple FADD chains
    float accA0 = 0.0f, accA1 = 0.0f, accB0 = 0.0f, accB1 = 0.0f;

    const ulonglong2* geo = s_geo + w * NGRP;
    const int ng = s_ng[w];
#pragma unroll 2
    for (int k = 0; k < ng; ++k) {
        ulonglong2 q = geo[k];                    // LDS.128 broadcast, shared

        u64 dxA = addx2(xip0, q.x);
        u64 dyA = addx2(yip0, q.y);
        u64 d2A = fmx2(dxA, dxA, mulx2(dyA, dyA));
        u64 dxB = addx2(xip1, q.x);
        u64 dyB = addx2(yip1, q.y);
        u64 d2B = fmx2(dxB, dxB, mulx2(dyB, dyB));

        float dA0, dA1, dB0, dB1;
        upk2(dA0, dA1, d2A);
        upk2(dB0, dB1, d2B);

        // per-pair LUT: clamp bits, index, LDS.64, fma  (no MUFU)
        {
            u32 b = __float_as_uint(dA0);
            b = b < LOB ? LOB : b;  b = b > HIB ? HIB : b;
            float2 sc = s_lut[(b >> 17) - IDX_BASE];
            accA0 += fmaf(dA0, sc.x, sc.y);
        }
        {
            u32 b = __float_as_uint(dA1);
            b = b < LOB ? LOB : b;  b = b > HIB ? HIB : b;
            float2 sc = s_lut[(b >> 17) - IDX_BASE];
            accA1 += fmaf(dA1, sc.x, sc.y);
        }
        {
            u32 b = __float_as_uint(dB0);
            b = b < LOB ? LOB : b;  b = b > HIB ? HIB : b;
            float2 sc = s_lut[(b >> 17) - IDX_BASE];
            accB0 += fmaf(dB0, sc.x, sc.y);
        }
        {
            u32 b = __float_as_uint(dB1);
            b = b < LOB ? LOB : b;  b = b > HIB ? HIB : b;
            float2 sc = s_lut[(b >> 17) - IDX_BASE];
            accB1 += fmaf(dB1, sc.x, sc.y);
        }
    }

    float p0 = accA0 + accA1;
    float p1 = accB0 + accB1;

    if (w > 0) { s_part[w - 1][lane] = p0; s_part[w - 1][lane + 32] = p1; }
    __syncthreads();
    if (w == 0) {
#pragma unroll
        for (int p = 0; p < NSITES - 1; ++p) {
            p0 += s_part[p][lane];
            p1 += s_part[p][lane + 32];
        }
        out[b0] = p0;
        out[b1] = p1;
    }
}

extern "C" void kernel_launch(void* const* d_in, const int* in_sizes, int n_in,
                              void* d_out, int out_size)
{
    const float* x    = (const float*)d_in[0];   // [B, 24]
    const float* nbr  = (const float*)d_in[1];   // [12, 64, 2]
    const float* mask = (const float*)d_in[2];   // [12, 64] (unused: FAR test)
    float* out        = (float*)d_out;           // [B]

    // ~30KB static smem per block; make sure carveout lets 5 blocks reside.
    cudaFuncSetAttribute(pot_energy_kernel,
                         cudaFuncAttributePreferredSharedMemoryCarveout, 70);

    int batch = in_sizes[0] / 24;                // 131072
    const int threads = 384;                     // 12 warps / 64 batch elems
    int blocks = batch / 64;                     // 2048
    pot_energy_kernel<<<blocks, threads>>>(x, nbr, mask, out, batch);
}

// round 16
// speedup vs baseline: 1.2423x; 1.2423x over previous
#include <cuda_runtime.h>

// PotEnergy1P: out[b] = sum_{i<12,k} exp(-r)/(r+0.01), r = |x[b,i]-nbr[i,k]|
// Hybrid kernel: each inner iteration processes TWO neighbor groups --
//   group k        (pre-scaled by log2e): MUFU recipe (2x sqrt + ex2.f16x2)
//   group nh+k     (unscaled):            smem LUT recipe (piecewise-linear
//                                         v(d2), divergent LDS.64 + FMA)
// so the MUFU pipe and the smem crossbar run concurrently per warp.
// rcp via packed 64-bit magic seed + 2 Newton (FMA pipe); packed f32x2 math.
// FAR padding -> sentinel (41,0): ex2 underflows / LUT bin is zero.
// Shape: block 384 = 12 warps (one site per warp), 64 elems/block,
// 2 batch elems per thread.

#define NSITES 12
#define NMAX   64
#define NGRP   32              // 2-neighbor groups per site

#define LUT_N      2624        // 41 octaves * 64
#define LUT_ZERO   2368        // idx >= this (u >= 512) -> slope=c=0
#define LOB        0x31800000u // bits(2^-28)
#define HIB        0x45FE0000u // bits of top bin (idx 2623)
#define IDX_BASE   6336        // exp field 99 << 6

typedef unsigned long long u64;
typedef unsigned int u32;

#define C_NEGLN2 0xBF317218BF317218ULL   // -ln(2)
#define C_NEGB   0xBC23D70ABC23D70AULL   // -0.01f
#define C_TWO    0x4000000040000000ULL   //  2.0f
#define C_NEG2   0xC0000000C0000000ULL   // -2.0f
#define MAGIC2   0x7EF311C37EF311C3ULL   // rcp seed magic, both lanes

__device__ __forceinline__ u64 pk2(float lo, float hi) {
    u64 r; asm("mov.b64 %0, {%1,%2};" : "=l"(r) : "f"(lo), "f"(hi)); return r;
}
__device__ __forceinline__ void upk2(float& lo, float& hi, u64 v) {
    asm("mov.b64 {%0,%1}, %2;" : "=f"(lo), "=f"(hi) : "l"(v));
}
__device__ __forceinline__ u64 addx2(u64 a, u64 b) {
    u64 d; asm("add.rn.f32x2 %0,%1,%2;" : "=l"(d) : "l"(a), "l"(b)); return d;
}
__device__ __forceinline__ u64 mulx2(u64 a, u64 b) {
    u64 d; asm("mul.rn.f32x2 %0,%1,%2;" : "=l"(d) : "l"(a), "l"(b)); return d;
}
__device__ __forceinline__ u64 fmx2(u64 a, u64 b, u64 c) {
    u64 d; asm("fma.rn.f32x2 %0,%1,%2,%3;" : "=l"(d) : "l"(a), "l"(b), "l"(c)); return d;
}
__device__ __forceinline__ float fsqrt_approx(float a) {
    float r; asm("sqrt.approx.f32 %0, %1;" : "=f"(r) : "f"(a)); return r;
}
// packed exp(-pair) via f16x2 (sign flip on ALU between cvt and ex2).
__device__ __forceinline__ u64 exp2n_f16x2(u64 sp) {
    float sl, sh; upk2(sl, sh, sp);
    u32 h, e2;
    asm("cvt.rn.f16x2.f32 %0, %1, %2;" : "=r"(h) : "f"(sh), "f"(sl));
    h ^= 0x80008000u;
    asm("ex2.approx.f16x2 %0, %1;" : "=r"(e2) : "r"(h));
    float el, eh;
    asm("{.reg .b16 l, hh; mov.b32 {l, hh}, %2;"
        " cvt.f32.f16 %0, l; cvt.f32.f16 %1, hh;}"
        : "=f"(el), "=f"(eh) : "r"(e2));
    return pk2(el, eh);
}
__device__ __forceinline__ u64 pkbits(float lo, float hi) {
    return (u64)__float_as_uint(lo) | ((u64)__float_as_uint(hi) << 32);
}

#define L2E 1.4426950408889634f

__global__ __launch_bounds__(384, 4)
void pot_energy_kernel(const float* __restrict__ x,
                       const float* __restrict__ nbr,
                       const float* __restrict__ mask,
                       float* __restrict__ out,
                       int batch)
{
    __shared__ ulonglong2 s_geo[NSITES * NGRP];   // 6 KB
    __shared__ float2     s_lut[LUT_N];           // 21 KB
    __shared__ int        s_ng[NSITES];
    __shared__ float      s_part[NSITES - 1][64]; // 2.75 KB

    if (threadIdx.x < NSITES) s_ng[threadIdx.x] = 0;
    __syncthreads();

    // ---- phase 1: count valid groups per site ----
    const int j    = threadIdx.x;                 // 384 threads = 384 groups
    const int base = j * 4;
    float nx0 = nbr[base + 0], ny0 = nbr[base + 1];
    float nx1 = nbr[base + 2], ny1 = nbr[base + 3];
    bool far0 = fabsf(nx0) > 1e5f;
    if (far0)              { nx0 = 41.0f; ny0 = 0.0f; }   // sentinel
    if (fabsf(nx1) > 1e5f) { nx1 = 41.0f; ny1 = 0.0f; }
    if (!far0) atomicAdd(&s_ng[j >> 5], 1);       // list is front-packed
    __syncthreads();

    // ---- phase 2: write geometry; first nh groups scaled by log2e (MUFU),
    //      groups [nh, ...) unscaled (LUT path) ----
    {
        int ng = s_ng[j >> 5];
        int nh = (ng + 1) >> 1;
        float sc = ((j & 31) < nh) ? L2E : 1.0f;
        ulonglong2 v;
        v.x = pkbits(-nx0 * sc, -nx1 * sc);
        v.y = pkbits(-ny0 * sc, -ny1 * sc);
        s_geo[j] = v;
    }

    // ---- build LUT: v(u) ~ fmaf(u, slope, c), 64 bins/octave ----
    for (int idx = threadIdx.x; idx < LUT_N; idx += blockDim.x) {
        float2 e;
        if (idx >= LUT_ZERO) {
            e.x = 0.0f; e.y = 0.0f;
        } else {
            u32 lob = (u32)(idx + IDX_BASE) << 17;
            u32 hib = lob + (1u << 17);
            float ulo = __uint_as_float(lob);
            float uhi = __uint_as_float(hib);
            float rlo = sqrtf(ulo), rhi = sqrtf(uhi);
            float flo = expf(-rlo) / (rlo + 0.01f);
            float fhi = expf(-rhi) / (rhi + 0.01f);
            float slope = (fhi - flo) / (uhi - ulo);
            e.x = slope;
            e.y = fmaf(-ulo, slope, flo);
        }
        s_lut[idx] = e;
    }
    __syncthreads();

    const int w    = threadIdx.x >> 5;            // warp = site 0..11
    const int lane = threadIdx.x & 31;
    const int b0   = blockIdx.x * 64 + lane;      // elem A
    const int b1   = b0 + 32;                     // elem B

    float2 v0 = *reinterpret_cast<const float2*>(x + (size_t)b0 * 24 + w * 2);
    float2 v1 = *reinterpret_cast<const float2*>(x + (size_t)b1 * 24 + w * 2);
    // scaled copies (MUFU path) and unscaled copies (LUT path)
    u64 xipA = pk2(v0.x * L2E, v0.x * L2E);
    u64 yipA = pk2(v0.y * L2E, v0.y * L2E);
    u64 xipB = pk2(v1.x * L2E, v1.x * L2E);
    u64 yipB = pk2(v1.y * L2E, v1.y * L2E);
    u64 uxA  = pk2(v0.x, v0.x);
    u64 uyA  = pk2(v0.y, v0.y);
    u64 uxB  = pk2(v1.x, v1.x);
    u64 uyB  = pk2(v1.y, v1.y);

    u64 acc0 = 0ULL, acc1 = 0ULL;                 // MUFU-path accumulators
    float lA0 = 0.f, lA1 = 0.f, lB0 = 0.f, lB1 = 0.f;  // LUT-path accs

    const ulonglong2* geo = s_geo + w * NGRP;
    const int ng = s_ng[w];
    const int nh = (ng + 1) >> 1;
    for (int k = 0; k < nh; ++k) {
        // ================= MUFU-recipe group k (scaled geo) =================
        {
            ulonglong2 q = geo[k];                // LDS.128 broadcast
            u64 dxA = addx2(xipA, q.x);
            u64 dyA = addx2(yipA, q.y);
            u64 d2A = fmx2(dxA, dxA, mulx2(dyA, dyA));
            u64 dxB = addx2(xipB, q.x);
            u64 dyB = addx2(yipB, q.y);
            u64 d2B = fmx2(dxB, dxB, mulx2(dyB, dyB));

            float dAl, dAh, dBl, dBh;
            upk2(dAl, dAh, d2A);
            upk2(dBl, dBh, d2B);
            float sAl = fsqrt_approx(dAl);        // MUFU
            float sAh = fsqrt_approx(dAh);
            float sBl = fsqrt_approx(dBl);
            float sBh = fsqrt_approx(dBh);
            u64 spA = pk2(sAl, sAh);
            u64 spB = pk2(sBl, sBh);

            u64 epA = exp2n_f16x2(spA);           // MUFU
            u64 epB = exp2n_f16x2(spB);

            u64 wnA = fmx2(spA, C_NEGLN2, C_NEGB);
            u64 wnB = fmx2(spB, C_NEGLN2, C_NEGB);
            u64 ynA = MAGIC2 - wnA;
            u64 ynB = MAGIC2 - wnB;
            u64 t1A = fmx2(wnA, ynA, C_NEG2);
            u64 t1B = fmx2(wnB, ynB, C_NEG2);
            u64 y1A = mulx2(ynA, t1A);
            u64 y1B = mulx2(ynB, t1B);
            u64 t2A = fmx2(wnA, y1A, C_TWO);
            u64 t2B = fmx2(wnB, y1B, C_TWO);
            u64 y2A = mulx2(y1A, t2A);
            u64 y2B = mulx2(y1B, t2B);
            acc0 = fmx2(epA, y2A, acc0);
            acc1 = fmx2(epB, y2B, acc1);
        }
        // ================= LUT-recipe group nh+k (unscaled geo) =============
        {
            ulonglong2 q = geo[nh + k];           // LDS.128 broadcast
            u64 dxA = addx2(uxA, q.x);
            u64 dyA = addx2(uyA, q.y);
            u64 d2A = fmx2(dxA, dxA, mulx2(dyA, dyA));
            u64 dxB = addx2(uxB, q.x);
            u64 dyB = addx2(uyB, q.y);
            u64 d2B = fmx2(dxB, dxB, mulx2(dyB, dyB));

            float dA0, dA1, dB0, dB1;
            upk2(dA0, dA1, d2A);
            upk2(dB0, dB1, d2B);
            {
                u32 b = __float_as_uint(dA0);
                b = b < LOB ? LOB : b;  b = b > HIB ? HIB : b;
                float2 sc = s_lut[(b >> 17) - IDX_BASE];
                lA0 += fmaf(dA0, sc.x, sc.y);
            }
            {
                u32 b = __float_as_uint(dA1);
                b = b < LOB ? LOB : b;  b = b > HIB ? HIB : b;
                float2 sc = s_lut[(b >> 17) - IDX_BASE];
                lA1 += fmaf(dA1, sc.x, sc.y);
            }
            {
                u32 b = __float_as_uint(dB0);
                b = b < LOB ? LOB : b;  b = b > HIB ? HIB : b;
                float2 sc = s_lut[(b >> 17) - IDX_BASE];
                lB0 += fmaf(dB0, sc.x, sc.y);
            }
            {
                u32 b = __float_as_uint(dB1);
                b = b < LOB ? LOB : b;  b = b > HIB ? HIB : b;
                float2 sc = s_lut[(b >> 17) - IDX_BASE];
                lB1 += fmaf(dB1, sc.x, sc.y);
            }
        }
    }

    float a0l, a0h, a1l, a1h;
    upk2(a0l, a0h, acc0);
    upk2(a1l, a1h, acc1);
    float p0 = a0l + a0h + lA0 + lA1;
    float p1 = a1l + a1h + lB0 + lB1;

    if (w > 0) { s_part[w - 1][lane] = p0; s_part[w - 1][lane + 32] = p1; }
    __syncthreads();
    if (w == 0) {
#pragma unroll
        for (int p = 0; p < NSITES - 1; ++p) {
            p0 += s_part[p][lane];
            p1 += s_part[p][lane + 32];
        }
        out[b0] = p0;
        out[b1] = p1;
    }
}

extern "C" void kernel_launch(void* const* d_in, const int* in_sizes, int n_in,
                              void* d_out, int out_size)
{
    const float* x    = (const float*)d_in[0];   // [B, 24]
    const float* nbr  = (const float*)d_in[1];   // [12, 64, 2]
    const float* mask = (const float*)d_in[2];   // [12, 64] (unused: FAR test)
    float* out        = (float*)d_out;           // [B]

    // ~30KB static smem/block; allow 4 resident blocks.
    cudaFuncSetAttribute(pot_energy_kernel,
                         cudaFuncAttributePreferredSharedMemoryCarveout, 70);

    int batch = in_sizes[0] / 24;                // 131072
    const int threads = 384;                     // 12 warps / 64 batch elems
    int blocks = batch / 64;                     // 2048
    pot_energy_kernel<<<blocks, threads>>>(x, nbr, mask, out, batch);
}